// round 5
// baseline (speedup 1.0000x reference)
#include <cuda_runtime.h>
#include <cuda_bf16.h>
#include <cstddef>

// SkipGram negative-sampling loss — persistent grid-stride kernel with a
// 2-deep software pipeline (double-buffered row gathers, idx prefetch).
// Inputs: pos_w[int32,B], pos_v[int32,B], neg_v[int32,B*5],
//         w_table[f32,V*128], v_table[f32,V*128]
// Output: float scalar loss = -(sum logsig(w·v) + sum_k logsig(-(nk·v)))

#define DIM 128
#define NEG 5
#define NROWS 7                 // w, v, 5 x neg
#define THREADS 128
#define WARPS_PER_BLOCK (THREADS / 32)
#define NUM_SMS 148
#define CTAS_PER_SM 4
#define GRID (NUM_SMS * CTAS_PER_SM)

__global__ void zero_out_kernel(float* out) { *out = 0.0f; }

__device__ __forceinline__ float log_sigmoid_fast(float x) {
    float e = __expf(-fabsf(x));
    return fminf(x, 0.0f) - __logf(1.0f + e);
}

__device__ __forceinline__ void load_idx(int e,
                                         const int* __restrict__ pw,
                                         const int* __restrict__ pv,
                                         const int* __restrict__ nv,
                                         int I[NROWS]) {
    I[0] = __ldg(pw + e);
    I[1] = __ldg(pv + e);
#pragma unroll
    for (int k = 0; k < NEG; k++) I[2 + k] = __ldg(nv + e * NEG + k);
}

__device__ __forceinline__ void issue_rows(const int I[NROWS],
                                           const float4* __restrict__ wt,
                                           const float4* __restrict__ vt,
                                           unsigned lane, float4 C[NROWS]) {
    // each row = 32 float4 granules; lane l takes granule l -> 512B coalesced
    C[0] = __ldg(wt + (unsigned)I[0] * 32u + lane);
    C[1] = __ldg(vt + (unsigned)I[1] * 32u + lane);
#pragma unroll
    for (int k = 0; k < NEG; k++)
        C[2 + k] = __ldg(vt + (unsigned)I[2 + k] * 32u + lane);
}

__device__ __forceinline__ void consume(const float4 C[NROWS], int lane, float& acc) {
    const float4 w4 = C[0];
    const float4 v4 = C[1];
    float dp = w4.x * v4.x + w4.y * v4.y + w4.z * v4.z + w4.w * v4.w;
    float dn[NEG];
#pragma unroll
    for (int k = 0; k < NEG; k++) {
        const float4 n4 = C[2 + k];
        dn[k] = n4.x * v4.x + n4.y * v4.y + n4.z * v4.z + n4.w * v4.w;
    }
#pragma unroll
    for (int off = 16; off > 0; off >>= 1) {
        dp += __shfl_xor_sync(0xFFFFFFFFu, dp, off);
#pragma unroll
        for (int k = 0; k < NEG; k++)
            dn[k] += __shfl_xor_sync(0xFFFFFFFFu, dn[k], off);
    }
    if (lane == 0) {
        float s = log_sigmoid_fast(dp);
#pragma unroll
        for (int k = 0; k < NEG; k++) s += log_sigmoid_fast(-dn[k]);
        acc += s;
    }
}

__global__ __launch_bounds__(THREADS, CTAS_PER_SM) void skipgram_loss_kernel(
    const int* __restrict__ pos_w,
    const int* __restrict__ pos_v,
    const int* __restrict__ neg_v,
    const float* __restrict__ w_table,
    const float* __restrict__ v_table,
    float* __restrict__ out,
    int batch)
{
    const unsigned lane = threadIdx.x & 31u;
    const int warp_in_block = threadIdx.x >> 5;
    const int gw = blockIdx.x * WARPS_PER_BLOCK + warp_in_block;
    const int stride = gridDim.x * WARPS_PER_BLOCK;

    const float4* wt4 = reinterpret_cast<const float4*>(w_table);
    const float4* vt4 = reinterpret_cast<const float4*>(v_table);

    float acc = 0.0f;

    // Software pipeline state: I[] holds indices for element `e` (the one about
    // to issue). Two row buffers alternate by iteration parity so that rows for
    // element e+1 are issued BEFORE rows for element e are consumed.
    float4 B0[NROWS], B1[NROWS];
    int I[NROWS];

    int e = gw;
    if (e < batch) load_idx(e, pos_w, pos_v, neg_v, I);

    bool have_prev = false;
    int parity = 0;

    while (true) {
        const bool cur_valid = (e < batch);

        // 1) issue row gathers for element e (bulk traffic) into buf[parity]
        if (parity == 0) {
            if (cur_valid) issue_rows(I, wt4, vt4, lane, B0);
        } else {
            if (cur_valid) issue_rows(I, wt4, vt4, lane, B1);
        }

        // 2) prefetch indices for the next element (overlaps row latency)
        const int en = e + stride;
        if (en < batch) load_idx(en, pos_w, pos_v, neg_v, I);

        // 3) consume the previous element's rows (issued one iteration ago,
        //    so their DRAM latency is largely hidden behind 1)+2) and the
        //    previous consume)
        if (have_prev) {
            if (parity == 0) consume(B1, lane, acc);
            else             consume(B0, lane, acc);
        }

        if (!cur_valid) break;
        have_prev = true;
        e = en;
        parity ^= 1;
    }

    // Block reduce (one value per warp, lane 0 holds it) -> one atomic per CTA.
    __shared__ float warp_sums[WARPS_PER_BLOCK];
    if (lane == 0) warp_sums[warp_in_block] = acc;
    __syncthreads();

    if (threadIdx.x == 0) {
        float bs = 0.0f;
#pragma unroll
        for (int i = 0; i < WARPS_PER_BLOCK; i++) bs += warp_sums[i];
        atomicAdd(out, -bs);   // loss = -(sum of logsigmoids)
    }
}

extern "C" void kernel_launch(void* const* d_in, const int* in_sizes, int n_in,
                              void* d_out, int out_size)
{
    const int*   pos_w   = (const int*)d_in[0];
    const int*   pos_v   = (const int*)d_in[1];
    const int*   neg_v   = (const int*)d_in[2];
    const float* w_table = (const float*)d_in[3];
    const float* v_table = (const float*)d_in[4];
    float* out = (float*)d_out;

    const int batch = in_sizes[0];

    zero_out_kernel<<<1, 1>>>(out);

    skipgram_loss_kernel<<<GRID, THREADS>>>(pos_w, pos_v, neg_v,
                                            w_table, v_table, out, batch);
}

// round 8
// speedup vs baseline: 1.3505x; 1.3505x over previous
#include <cuda_runtime.h>
#include <cuda_bf16.h>
#include <cstddef>

// SkipGram negative-sampling loss — persistent grid-stride, max-occupancy,
// flat per-element body with index prefetch (no row double-buffering).
// Inputs: pos_w[int32,B], pos_v[int32,B], neg_v[int32,B*5],
//         w_table[f32,V*128], v_table[f32,V*128]
// Output: float scalar loss = -(sum logsig(w·v) + sum_k logsig(-(nk·v)))

#define DIM 128
#define NEG 5
#define NROWS 7
#define THREADS 256
#define WARPS_PER_BLOCK (THREADS / 32)
#define NUM_SMS 148
#define CTAS_PER_SM 6
#define GRID (NUM_SMS * CTAS_PER_SM)

__global__ void zero_out_kernel(float* out) { *out = 0.0f; }

__device__ __forceinline__ float log_sigmoid_fast(float x) {
    float e = __expf(-fabsf(x));
    return fminf(x, 0.0f) - __logf(1.0f + e);
}

__device__ __forceinline__ void load_idx(int e,
                                         const int* __restrict__ pw,
                                         const int* __restrict__ pv,
                                         const int* __restrict__ nv,
                                         int I[NROWS]) {
    I[0] = __ldg(pw + e);
    I[1] = __ldg(pv + e);
#pragma unroll
    for (int k = 0; k < NEG; k++) I[2 + k] = __ldg(nv + e * NEG + k);
}

__global__ __launch_bounds__(THREADS, CTAS_PER_SM) void skipgram_loss_kernel(
    const int* __restrict__ pos_w,
    const int* __restrict__ pos_v,
    const int* __restrict__ neg_v,
    const float* __restrict__ w_table,
    const float* __restrict__ v_table,
    float* __restrict__ out,
    int batch)
{
    const unsigned lane = threadIdx.x & 31u;
    const int warp_in_block = threadIdx.x >> 5;
    const int gw = blockIdx.x * WARPS_PER_BLOCK + warp_in_block;
    const int stride = GRID * WARPS_PER_BLOCK;

    const float4* wt4 = reinterpret_cast<const float4*>(w_table);
    const float4* vt4 = reinterpret_cast<const float4*>(v_table);

    float acc = 0.0f;

    int I[NROWS];
    int e = gw;
    if (e < batch) load_idx(e, pos_w, pos_v, neg_v, I);

    while (e < batch) {
        // 1) Issue all 7 row gathers for element e (front-batched; each row is
        //    32 float4 granules, lane l takes granule l -> 512B coalesced).
        float4 w4 = __ldg(wt4 + (unsigned)I[0] * 32u + lane);
        float4 v4 = __ldg(vt4 + (unsigned)I[1] * 32u + lane);
        float4 n4[NEG];
#pragma unroll
        for (int k = 0; k < NEG; k++)
            n4[k] = __ldg(vt4 + (unsigned)I[2 + k] * 32u + lane);

        // 2) Prefetch next element's indices (L2-resident, ~250cyc) so the
        //    idx->row dependency of the NEXT iteration is pre-resolved while
        //    this element's row loads (~600cyc) are in flight.
        const int en = e + stride;
        if (en < batch) load_idx(en, pos_w, pos_v, neg_v, I);

        // 3) Consume: 6 dots, warp butterfly reduce, logsigmoid on lane 0.
        float dp = w4.x * v4.x + w4.y * v4.y + w4.z * v4.z + w4.w * v4.w;
        float dn[NEG];
#pragma unroll
        for (int k = 0; k < NEG; k++)
            dn[k] = n4[k].x * v4.x + n4[k].y * v4.y + n4[k].z * v4.z + n4[k].w * v4.w;

#pragma unroll
        for (int off = 16; off > 0; off >>= 1) {
            dp += __shfl_xor_sync(0xFFFFFFFFu, dp, off);
#pragma unroll
            for (int k = 0; k < NEG; k++)
                dn[k] += __shfl_xor_sync(0xFFFFFFFFu, dn[k], off);
        }

        if (lane == 0) {
            float s = log_sigmoid_fast(dp);
#pragma unroll
            for (int k = 0; k < NEG; k++) s += log_sigmoid_fast(-dn[k]);
            acc += s;
        }

        e = en;
    }

    // Block reduce (one value per warp) -> one atomic per CTA.
    __shared__ float warp_sums[WARPS_PER_BLOCK];
    if (lane == 0) warp_sums[warp_in_block] = acc;
    __syncthreads();

    if (threadIdx.x == 0) {
        float bs = 0.0f;
#pragma unroll
        for (int i = 0; i < WARPS_PER_BLOCK; i++) bs += warp_sums[i];
        atomicAdd(out, -bs);   // loss = -(sum of logsigmoids)
    }
}

extern "C" void kernel_launch(void* const* d_in, const int* in_sizes, int n_in,
                              void* d_out, int out_size)
{
    const int*   pos_w   = (const int*)d_in[0];
    const int*   pos_v   = (const int*)d_in[1];
    const int*   neg_v   = (const int*)d_in[2];
    const float* w_table = (const float*)d_in[3];
    const float* v_table = (const float*)d_in[4];
    float* out = (float*)d_out;

    const int batch = in_sizes[0];

    zero_out_kernel<<<1, 1>>>(out);

    skipgram_loss_kernel<<<GRID, THREADS>>>(pos_w, pos_v, neg_v,
                                            w_table, v_table, out, batch);
}